// round 3
// baseline (speedup 1.0000x reference)
#include <cuda_runtime.h>
#include <stdint.h>

#define NC 80
#define NP 30000
#define NG 800
#define NB 16384   // score buckets (2^14): trunc(score*16384) is exact & monotone

// ---------------- scratch (static device globals; no allocation) ----------------
__device__ unsigned long long g_slot[(size_t)NC * NP];   // (~score_bits<<32)|idx, per class contiguous
__device__ int   g_rank[NC * NP];     // rank of pred idx within class (0 = highest score)
__device__ int   g_match[NC * NP];    // matched gt index if valid else -1
__device__ int   g_hist[NC * NB];
__device__ int   g_base[NC * NB];
__device__ int   g_cursor[NC * NB];
__device__ int   g_first[NC * NG];    // min rank among valid preds matching gt
__device__ int   g_tpcnt[NC];
__device__ int   g_tprank[NC * 1024];
__device__ float g_ap[NC];

// ---------------- K0: init ----------------
__global__ void k_init() {
    int i = blockIdx.x * blockDim.x + threadIdx.x;
    if (i < NC * NB) g_hist[i] = 0;
    if (i < NC * NG) g_first[i] = NP;
    if (i < NC)      g_tpcnt[i] = 0;
}

// ---------------- K1: histogram of score buckets ----------------
__global__ void k_hist(const float* __restrict__ pred) {
    int i = blockIdx.x * blockDim.x + threadIdx.x;
    if (i >= NC * NP) return;
    float s = pred[(size_t)i * 7 + 2];
    int b = (int)(s * 16384.0f);
    b = max(0, min(b, NB - 1));
    int c = i / NP;
    atomicAdd(&g_hist[c * NB + b], 1);
}

// ---------------- K2: per-class suffix-exclusive scan (descending order base) ----------------
__global__ void k_scan() {
    __shared__ int ssum[1024];
    int c = blockIdx.x, t = threadIdx.x;
    int h[16], tot = 0;
    int off0 = c * NB + t * 16;
#pragma unroll
    for (int j = 0; j < 16; j++) { h[j] = g_hist[off0 + j]; tot += h[j]; }
    ssum[t] = tot;
    __syncthreads();
    // inclusive suffix sum over 1024 chunk sums
    for (int off = 1; off < 1024; off <<= 1) {
        int v = (t + off < 1024) ? ssum[t + off] : 0;
        __syncthreads();
        ssum[t] += v;
        __syncthreads();
    }
    int running = ssum[t] - tot;   // exclusive suffix over later chunks
#pragma unroll
    for (int j = 15; j >= 0; j--) {
        g_base[off0 + j]   = running;
        g_cursor[off0 + j] = running;
        running += h[j];
    }
}

// ---------------- K3: scatter into bucket slots ----------------
__global__ void k_scatter(const float* __restrict__ pred) {
    int i = blockIdx.x * blockDim.x + threadIdx.x;
    if (i >= NC * NP) return;
    float s = pred[(size_t)i * 7 + 2];
    int b = (int)(s * 16384.0f);
    b = max(0, min(b, NB - 1));
    int c = i / NP, p = i - c * NP;
    unsigned int sb = __float_as_uint(s);
    int slot = atomicAdd(&g_cursor[c * NB + b], 1);
    g_slot[(size_t)c * NP + slot] = ((unsigned long long)(~sb) << 32) | (unsigned int)p;
}

// ---------------- K4: tiny per-bucket insertion sort + write ranks ----------------
__global__ void k_bsort() {
    int i = blockIdx.x * blockDim.x + threadIdx.x;
    if (i >= NC * NB) return;
    int m = g_hist[i];
    if (m == 0) return;
    int c = i / NB;
    int base = g_base[i];
    unsigned long long* s = g_slot + (size_t)c * NP + base;
    for (int a = 1; a < m; a++) {
        unsigned long long k = s[a];
        int j = a - 1;
        while (j >= 0 && s[j] > k) { s[j + 1] = s[j]; j--; }
        s[j + 1] = k;
    }
    for (int t = 0; t < m; t++) {
        int idx = (int)(s[t] & 0xffffffffULL);
        g_rank[c * NP + idx] = base + t;
    }
}

// ---------------- K5: match (dominant kernel; 2 preds per thread for ILP) ----------------
__global__ void __launch_bounds__(128) k_match(const float* __restrict__ pred,
                                               const float* __restrict__ gt) {
    __shared__ float4 sg[NG];
    __shared__ float  sa[NG];
    int c = blockIdx.y;
    for (int g = threadIdx.x; g < NG; g += blockDim.x) {
        const float* gp = gt + ((size_t)c * NG + g) * 7;
        float x1 = gp[3], y1 = gp[4], x2 = gp[5], y2 = gp[6];
        sg[g] = make_float4(x1, y1, x2, y2);
        sa[g] = (x2 - x1) * (y2 - y1);
    }
    __syncthreads();

    int p0 = blockIdx.x * 256 + threadIdx.x;      // two preds per thread
    int p1 = p0 + 128;
    bool v0 = p0 < NP, v1 = p1 < NP;
    if (!v0) return;

    const float* pp0 = pred + ((size_t)c * NP + p0) * 7;
    float ax1 = pp0[3], ay1 = pp0[4], ax2 = pp0[5], ay2 = pp0[6];
    float areaA = (ax2 - ax1) * (ay2 - ay1);

    // second pred (duplicate first if out of range to keep code uniform)
    const float* pp1 = pred + ((size_t)c * NP + (v1 ? p1 : p0)) * 7;
    float bx1 = pp1[3], by1 = pp1[4], bx2 = pp1[5], by2 = pp1[6];
    float areaB = (bx2 - bx1) * (by2 - by1);

    float ai = 0.0f, ad = 1.0f; int ag = 0;
    float bi = 0.0f, bd = 1.0f; int bg = 0;
#pragma unroll 4
    for (int g = 0; g < NG; g++) {
        float4 q = sg[g];
        float ga = sa[g];

        float w0 = fminf(ax2, q.z) - fmaxf(ax1, q.x);
        float h0 = fminf(ay2, q.w) - fmaxf(ay1, q.y);
        w0 = fmaxf(w0, 0.0f); h0 = fmaxf(h0, 0.0f);
        float i0 = w0 * h0;
        float d0 = areaA + ga - i0;
        if (i0 * ad > ai * d0) { ai = i0; ad = d0; ag = g; }

        float w1 = fminf(bx2, q.z) - fmaxf(bx1, q.x);
        float h1 = fminf(by2, q.w) - fmaxf(by1, q.y);
        w1 = fmaxf(w1, 0.0f); h1 = fmaxf(h1, 0.0f);
        float i1 = w1 * h1;
        float d1 = areaB + ga - i1;
        if (i1 * bd > bi * d1) { bi = i1; bd = d1; bg = g; }
    }

    {
        int idx = c * NP + p0;
        float iou = ai / (ad + 1e-9f);
        if (iou > 0.5f) {
            g_match[idx] = ag;
            atomicMin(&g_first[c * NG + ag], g_rank[idx]);
        } else {
            g_match[idx] = -1;
        }
    }
    if (v1) {
        int idx = c * NP + p1;
        float iou = bi / (bd + 1e-9f);
        if (iou > 0.5f) {
            g_match[idx] = bg;
            atomicMin(&g_first[c * NG + bg], g_rank[idx]);
        } else {
            g_match[idx] = -1;
        }
    }
}

// ---------------- K6: collect true positives ----------------
__global__ void k_tp() {
    int i = blockIdx.x * blockDim.x + threadIdx.x;
    if (i >= NC * NP) return;
    int m = g_match[i];
    if (m < 0) return;
    int c = i / NP;
    int r = g_rank[i];
    if (g_first[c * NG + m] == r) {
        int t = atomicAdd(&g_tpcnt[c], 1);
        g_tprank[c * 1024 + t] = r;
    }
}

// ---------------- K7: per-class AP ----------------
__global__ void k_ap() {
    __shared__ int    sr[1024];
    __shared__ double red[1024];
    int c = blockIdx.x, t = threadIdx.x;
    int n = g_tpcnt[c];
    sr[t] = (t < n) ? g_tprank[c * 1024 + t] : 0x7fffffff;
    __syncthreads();
    double term = 0.0;
    if (t < n) {
        int r = sr[t];
        int cnt = 1;                       // ctp at position r
        for (int j = 0; j < n; j++) cnt += (sr[j] < r) ? 1 : 0;
        if (r > 0) {
            float p1 = (float)cnt / (float)(r + 1);        // precision[r]
            float p0 = (float)(cnt - 1) / (float)r;        // precision[r-1]
            term = 0.5 * ((double)p1 + (double)p0);
        }
    }
    red[t] = term;
    __syncthreads();
    for (int s = 512; s > 0; s >>= 1) {
        if (t < s) red[t] += red[t + s];
        __syncthreads();
    }
    if (t == 0) g_ap[c] = (float)(red[0] / (double)NG);
}

// ---------------- K8: mean over classes ----------------
__global__ void k_mean(float* __restrict__ out) {
    __shared__ double red[128];
    int t = threadIdx.x;
    red[t] = (t < NC) ? (double)g_ap[t] : 0.0;
    __syncthreads();
    for (int s = 64; s > 0; s >>= 1) {
        if (t < s) red[t] += red[t + s];
        __syncthreads();
    }
    if (t == 0) out[0] = (float)(red[0] / (double)NC);
}

// ---------------- launcher ----------------
extern "C" void kernel_launch(void* const* d_in, const int* in_sizes, int n_in,
                              void* d_out, int out_size) {
    const float* pred;
    const float* gt;
    if (in_sizes[0] == NC * NP * 7) { pred = (const float*)d_in[0]; gt = (const float*)d_in[1]; }
    else                            { pred = (const float*)d_in[1]; gt = (const float*)d_in[0]; }

    const int NTOT = NC * NP;
    k_init<<<(NC * NB + 255) / 256, 256>>>();
    k_hist<<<(NTOT + 255) / 256, 256>>>(pred);
    k_scan<<<NC, 1024>>>();
    k_scatter<<<(NTOT + 255) / 256, 256>>>(pred);
    k_bsort<<<(NC * NB + 255) / 256, 256>>>();
    dim3 mg((NP + 255) / 256, NC);
    k_match<<<mg, 128>>>(pred, gt);
    k_tp<<<(NTOT + 255) / 256, 256>>>();
    k_ap<<<NC, 1024>>>();
    k_mean<<<1, 128>>>((float*)d_out);
}

// round 4
// speedup vs baseline: 1.4207x; 1.4207x over previous
#include <cuda_runtime.h>
#include <stdint.h>

#define NC 80
#define NP 30000
#define NG 800
#define NB 16384   // score buckets (2^14): trunc(score*16384) is exact & monotone

// ---------------- scratch (static device globals; no allocation) ----------------
__device__ unsigned long long g_slot[(size_t)NC * NP];   // (~score_bits<<32)|idx, per class contiguous
__device__ int   g_rank[NC * NP];     // rank of pred idx within class (0 = highest score)
__device__ int   g_match[NC * NP];    // matched (original) gt index if valid else -1
__device__ unsigned int g_sbits[NC * NP];  // score bits cache (hist -> scatter)
__device__ int   g_hist[NC * NB];
__device__ int   g_base[NC * NB];
__device__ int   g_cursor[NC * NB];
__device__ int   g_first[NC * NG];    // min rank among valid preds matching gt
__device__ int   g_tpcnt[NC];
__device__ int   g_tprank[NC * 1024];
__device__ float g_ap[NC];
// sorted-by-x1 gt arrays
__device__ float4 g_sgbox[NC * NG];
__device__ float  g_sgarea[NC * NG];
__device__ int    g_sgidx[NC * NG];
__device__ float  g_sgx1[NC * NG];
__device__ float  g_gwmax[NC];

// ---------------- K0: init ----------------
__global__ void k_init() {
    int i = blockIdx.x * blockDim.x + threadIdx.x;
    if (i < NC * NB) g_hist[i] = 0;
    if (i < NC * NG) g_first[i] = NP;
    if (i < NC)      g_tpcnt[i] = 0;
}

// ---------------- K1: histogram of score buckets (+cache score bits) ----------------
__global__ void k_hist(const float* __restrict__ pred) {
    int i = blockIdx.x * blockDim.x + threadIdx.x;
    if (i >= NC * NP) return;
    float s = pred[(size_t)i * 7 + 2];
    g_sbits[i] = __float_as_uint(s);
    int b = (int)(s * 16384.0f);
    b = max(0, min(b, NB - 1));
    int c = i / NP;
    atomicAdd(&g_hist[c * NB + b], 1);
}

// ---------------- K2: per-class suffix-exclusive scan (descending order base) ----------------
__global__ void k_scan() {
    __shared__ int ssum[1024];
    int c = blockIdx.x, t = threadIdx.x;
    int h[16], tot = 0;
    int off0 = c * NB + t * 16;
#pragma unroll
    for (int j = 0; j < 16; j++) { h[j] = g_hist[off0 + j]; tot += h[j]; }
    ssum[t] = tot;
    __syncthreads();
    for (int off = 1; off < 1024; off <<= 1) {
        int v = (t + off < 1024) ? ssum[t + off] : 0;
        __syncthreads();
        ssum[t] += v;
        __syncthreads();
    }
    int running = ssum[t] - tot;   // exclusive suffix over later chunks
#pragma unroll
    for (int j = 15; j >= 0; j--) {
        g_base[off0 + j]   = running;
        g_cursor[off0 + j] = running;
        running += h[j];
    }
}

// ---------------- K3: scatter into bucket slots (reads cached score bits) ----------------
__global__ void k_scatter() {
    int i = blockIdx.x * blockDim.x + threadIdx.x;
    if (i >= NC * NP) return;
    unsigned int sb = g_sbits[i];
    float s = __uint_as_float(sb);
    int b = (int)(s * 16384.0f);
    b = max(0, min(b, NB - 1));
    int c = i / NP, p = i - c * NP;
    int slot = atomicAdd(&g_cursor[c * NB + b], 1);
    g_slot[(size_t)c * NP + slot] = ((unsigned long long)(~sb) << 32) | (unsigned int)p;
}

// ---------------- K4: tiny per-bucket insertion sort + write ranks ----------------
__global__ void k_bsort() {
    int i = blockIdx.x * blockDim.x + threadIdx.x;
    if (i >= NC * NB) return;
    int m = g_hist[i];
    if (m == 0) return;
    int c = i / NB;
    int base = g_base[i];
    unsigned long long* s = g_slot + (size_t)c * NP + base;
    for (int a = 1; a < m; a++) {
        unsigned long long k = s[a];
        int j = a - 1;
        while (j >= 0 && s[j] > k) { s[j + 1] = s[j]; j--; }
        s[j + 1] = k;
    }
    for (int t = 0; t < m; t++) {
        int idx = (int)(s[t] & 0xffffffffULL);
        g_rank[c * NP + idx] = base + t;
    }
}

// ---------------- K4b: per-class bitonic sort of gts by x1 ----------------
__global__ void k_gtsort(const float* __restrict__ gt) {
    __shared__ unsigned long long key[1024];
    __shared__ float swm[1024];
    int c = blockIdx.x, t = threadIdx.x;
    float w = 0.0f;
    if (t < NG) {
        const float* gp = gt + ((size_t)c * NG + t) * 7;
        float x1 = gp[3];
        key[t] = ((unsigned long long)__float_as_uint(x1) << 32) | (unsigned int)t;
        w = gp[5] - x1;
    } else {
        key[t] = 0xFFFFFFFFFFFFFFFFULL;
    }
    swm[t] = w;
    __syncthreads();
    for (int k2 = 2; k2 <= 1024; k2 <<= 1) {
        for (int j = k2 >> 1; j > 0; j >>= 1) {
            int ixj = t ^ j;
            if (ixj > t) {
                bool up = ((t & k2) == 0);
                unsigned long long a = key[t], b = key[ixj];
                if ((a > b) == up) { key[t] = b; key[ixj] = a; }
            }
            __syncthreads();
        }
    }
    for (int s = 512; s > 0; s >>= 1) {
        if (t < s) swm[t] = fmaxf(swm[t], swm[t + s]);
        __syncthreads();
    }
    if (t == 0) g_gwmax[c] = swm[0];
    if (t < NG) {
        int oi = (int)(key[t] & 0xffffffffULL);
        const float* gp = gt + ((size_t)c * NG + oi) * 7;
        float x1 = gp[3], y1 = gp[4], x2 = gp[5], y2 = gp[6];
        int o = c * NG + t;
        g_sgbox[o]  = make_float4(x1, y1, x2, y2);
        g_sgarea[o] = (x2 - x1) * (y2 - y1);
        g_sgidx[o]  = oi;
        g_sgx1[o]   = x1;
    }
}

// ---------------- K5: match (dominant kernel; x-window pruned) ----------------
__global__ void __launch_bounds__(256) k_match(const float* __restrict__ pred) {
    __shared__ float4 sg[NG];
    __shared__ float  sa[NG];
    __shared__ int    si[NG];
    __shared__ float  sx[NG];
    __shared__ float  s_wmax;
    int c = blockIdx.y;
    for (int g = threadIdx.x; g < NG; g += blockDim.x) {
        int o = c * NG + g;
        sg[g] = g_sgbox[o];
        sa[g] = g_sgarea[o];
        si[g] = g_sgidx[o];
        sx[g] = g_sgx1[o];
    }
    if (threadIdx.x == 0) s_wmax = g_gwmax[c];
    __syncthreads();

    int p = blockIdx.x * blockDim.x + threadIdx.x;
    if (p >= NP) return;
    const float* pp = pred + ((size_t)c * NP + p) * 7;
    float ax1 = pp[3], ay1 = pp[4], ax2 = pp[5], ay2 = pp[6];
    float areaA = (ax2 - ax1) * (ay2 - ay1);

    // candidates: gx1 in [ax1 - wmax, ax2) — superset of all gts with inter>0
    float loval = ax1 - s_wmax;
    int lo = 0;
    {
        int n = NG;
        while (n > 0) {
            int half = n >> 1, mid = lo + half;
            if (sx[mid] < loval) { lo = mid + 1; n -= half + 1; }
            else n = half;
        }
    }
    int hi;
    {
        int b = lo, n = NG - lo;
        while (n > 0) {
            int half = n >> 1, mid = b + half;
            if (sx[mid] < ax2) { b = mid + 1; n -= half + 1; }
            else n = half;
        }
        hi = b;
    }

    float bi = 0.0f, bd = 1.0f;
    int bgi = 0x7fffffff;
#pragma unroll 4
    for (int g = lo; g < hi; g++) {
        float4 q = sg[g];
        float w = fminf(ax2, q.z) - fmaxf(ax1, q.x);
        float h = fminf(ay2, q.w) - fmaxf(ay1, q.y);
        w = fmaxf(w, 0.0f);
        h = fmaxf(h, 0.0f);
        float inter = w * h;
        float den = areaA + sa[g] - inter;
        // iou(g) > iou(best) <=> inter*bd > bi*den (den, bd > 0); ties -> smaller orig idx
        float l = inter * bd, r = bi * den;
        int gi = si[g];
        bool better = (l > r) || ((l == r) && (gi < bgi));
        if (better) { bi = inter; bd = den; bgi = gi; }
    }

    int idx = c * NP + p;
    float iou = bi / (bd + 1e-9f);
    if (iou > 0.5f) {
        g_match[idx] = bgi;
        atomicMin(&g_first[c * NG + bgi], g_rank[idx]);
    } else {
        g_match[idx] = -1;
    }
}

// ---------------- K6: collect true positives ----------------
__global__ void k_tp() {
    int i = blockIdx.x * blockDim.x + threadIdx.x;
    if (i >= NC * NP) return;
    int m = g_match[i];
    if (m < 0) return;
    int c = i / NP;
    int r = g_rank[i];
    if (g_first[c * NG + m] == r) {
        int t = atomicAdd(&g_tpcnt[c], 1);
        g_tprank[c * 1024 + t] = r;
    }
}

// ---------------- K7: per-class AP ----------------
__global__ void k_ap() {
    __shared__ int    sr[1024];
    __shared__ double red[1024];
    int c = blockIdx.x, t = threadIdx.x;
    int n = g_tpcnt[c];
    sr[t] = (t < n) ? g_tprank[c * 1024 + t] : 0x7fffffff;
    __syncthreads();
    double term = 0.0;
    if (t < n) {
        int r = sr[t];
        int cnt = 1;                       // ctp at position r
        for (int j = 0; j < n; j++) cnt += (sr[j] < r) ? 1 : 0;
        if (r > 0) {
            float p1 = (float)cnt / (float)(r + 1);        // precision[r]
            float p0 = (float)(cnt - 1) / (float)r;        // precision[r-1]
            term = 0.5 * ((double)p1 + (double)p0);
        }
    }
    red[t] = term;
    __syncthreads();
    for (int s = 512; s > 0; s >>= 1) {
        if (t < s) red[t] += red[t + s];
        __syncthreads();
    }
    if (t == 0) g_ap[c] = (float)(red[0] / (double)NG);
}

// ---------------- K8: mean over classes ----------------
__global__ void k_mean(float* __restrict__ out) {
    __shared__ double red[128];
    int t = threadIdx.x;
    red[t] = (t < NC) ? (double)g_ap[t] : 0.0;
    __syncthreads();
    for (int s = 64; s > 0; s >>= 1) {
        if (t < s) red[t] += red[t + s];
        __syncthreads();
    }
    if (t == 0) out[0] = (float)(red[0] / (double)NC);
}

// ---------------- launcher ----------------
extern "C" void kernel_launch(void* const* d_in, const int* in_sizes, int n_in,
                              void* d_out, int out_size) {
    const float* pred;
    const float* gt;
    if (in_sizes[0] == NC * NP * 7) { pred = (const float*)d_in[0]; gt = (const float*)d_in[1]; }
    else                            { pred = (const float*)d_in[1]; gt = (const float*)d_in[0]; }

    const int NTOT = NC * NP;
    k_init<<<(NC * NB + 255) / 256, 256>>>();
    k_hist<<<(NTOT + 255) / 256, 256>>>(pred);
    k_scan<<<NC, 1024>>>();
    k_scatter<<<(NTOT + 255) / 256, 256>>>();
    k_bsort<<<(NC * NB + 255) / 256, 256>>>();
    k_gtsort<<<NC, 1024>>>(gt);
    dim3 mg((NP + 255) / 256, NC);
    k_match<<<mg, 256>>>(pred);
    k_tp<<<(NTOT + 255) / 256, 256>>>();
    k_ap<<<NC, 1024>>>();
    k_mean<<<1, 128>>>((float*)d_out);
}

// round 5
// speedup vs baseline: 1.7260x; 1.2149x over previous
#include <cuda_runtime.h>
#include <stdint.h>

#define NC 80
#define NP 30000
#define NG 800
#define NB 16384   // score buckets (2^14)
#define NXB 256    // x-position buckets for pred locality sort

// ---------------- scratch (static device globals; no allocation) ----------------
__device__ unsigned long long g_slot[(size_t)NC * NP];
__device__ int   g_rank[NC * NP];
__device__ int   g_match[NC * NP];
__device__ unsigned int g_sbits[NC * NP];
__device__ int   g_hist[NC * NB];
__device__ int   g_base[NC * NB];
__device__ int   g_cursor[NC * NB];
__device__ int   g_xhist[NC * NXB];
__device__ int   g_xcursor[NC * NXB];
__device__ int   g_first[NC * NG];
__device__ int   g_tpcnt[NC];
__device__ int   g_tprank[NC * 1024];
__device__ float g_ap[NC];
// preds sorted by x-bucket
__device__ float4 g_pbox[(size_t)NC * NP];
__device__ int    g_pidx[NC * NP];
// gts sorted by x1
__device__ float4 g_sgbox[NC * NG];
__device__ float  g_sgarea[NC * NG];
__device__ int    g_sgidx[NC * NG];
__device__ float  g_sgx1[NC * NG];
__device__ float  g_gwmax[NC];

// ---------------- K0: init ----------------
__global__ void k_init() {
    int i = blockIdx.x * blockDim.x + threadIdx.x;
    if (i < NC * NB)  g_hist[i] = 0;
    if (i < NC * NXB) g_xhist[i] = 0;
    if (i < NC * NG)  g_first[i] = NP;
    if (i < NC)       g_tpcnt[i] = 0;
}

__device__ __forceinline__ int xbucket(float x1) {
    int b = (int)(x1 * (1.0f / 1024.0f) * (float)NXB);
    return max(0, min(b, NXB - 1));
}

// ---------------- K1: both histograms in one pred pass ----------------
__global__ void k_hist(const float* __restrict__ pred) {
    int i = blockIdx.x * blockDim.x + threadIdx.x;
    if (i >= NC * NP) return;
    const float* pp = pred + (size_t)i * 7;
    float s = pp[2];
    float x1 = pp[3];
    g_sbits[i] = __float_as_uint(s);
    int b = (int)(s * 16384.0f);
    b = max(0, min(b, NB - 1));
    int c = i / NP;
    atomicAdd(&g_hist[c * NB + b], 1);
    atomicAdd(&g_xhist[c * NXB + xbucket(x1)], 1);
}

// ---------------- K2: per-class suffix scan of score buckets ----------------
__global__ void k_scan() {
    __shared__ int ssum[1024];
    int c = blockIdx.x, t = threadIdx.x;
    int h[16], tot = 0;
    int off0 = c * NB + t * 16;
#pragma unroll
    for (int j = 0; j < 16; j++) { h[j] = g_hist[off0 + j]; tot += h[j]; }
    ssum[t] = tot;
    __syncthreads();
    for (int off = 1; off < 1024; off <<= 1) {
        int v = (t + off < 1024) ? ssum[t + off] : 0;
        __syncthreads();
        ssum[t] += v;
        __syncthreads();
    }
    int running = ssum[t] - tot;
#pragma unroll
    for (int j = 15; j >= 0; j--) {
        g_base[off0 + j]   = running;
        g_cursor[off0 + j] = running;
        running += h[j];
    }
}

// ---------------- K2b: per-class ascending exclusive scan of x buckets ----------------
__global__ void k_xscan() {
    __shared__ int sh[NXB];
    int c = blockIdx.x, t = threadIdx.x;
    sh[t] = g_xhist[c * NXB + t];
    __syncthreads();
    int v = sh[t];
    for (int off = 1; off < NXB; off <<= 1) {
        int u = (t >= off) ? sh[t - off] : 0;
        __syncthreads();
        sh[t] += u;
        __syncthreads();
    }
    g_xcursor[c * NXB + t] = sh[t] - v;   // exclusive prefix
}

// ---------------- K3: scatter score slots ----------------
__global__ void k_scatter() {
    int i = blockIdx.x * blockDim.x + threadIdx.x;
    if (i >= NC * NP) return;
    unsigned int sb = g_sbits[i];
    float s = __uint_as_float(sb);
    int b = (int)(s * 16384.0f);
    b = max(0, min(b, NB - 1));
    int c = i / NP, p = i - c * NP;
    int slot = atomicAdd(&g_cursor[c * NB + b], 1);
    g_slot[(size_t)c * NP + slot] = ((unsigned long long)(~sb) << 32) | (unsigned int)p;
}

// ---------------- K3b: scatter preds into x-sorted order ----------------
__global__ void k_xscatter(const float* __restrict__ pred) {
    int i = blockIdx.x * blockDim.x + threadIdx.x;
    if (i >= NC * NP) return;
    const float* pp = pred + (size_t)i * 7;
    float x1 = pp[3], y1 = pp[4], x2 = pp[5], y2 = pp[6];
    int c = i / NP, p = i - c * NP;
    int slot = atomicAdd(&g_xcursor[c * NXB + xbucket(x1)], 1);
    size_t o = (size_t)c * NP + slot;
    g_pbox[o] = make_float4(x1, y1, x2, y2);
    g_pidx[c * NP + slot] = p;
}

// ---------------- K4: per-bucket insertion sort + ranks ----------------
__global__ void k_bsort() {
    int i = blockIdx.x * blockDim.x + threadIdx.x;
    if (i >= NC * NB) return;
    int m = g_hist[i];
    if (m == 0) return;
    int c = i / NB;
    int base = g_base[i];
    unsigned long long* s = g_slot + (size_t)c * NP + base;
    for (int a = 1; a < m; a++) {
        unsigned long long k = s[a];
        int j = a - 1;
        while (j >= 0 && s[j] > k) { s[j + 1] = s[j]; j--; }
        s[j + 1] = k;
    }
    for (int t = 0; t < m; t++) {
        int idx = (int)(s[t] & 0xffffffffULL);
        g_rank[c * NP + idx] = base + t;
    }
}

// ---------------- K4b: per-class bitonic sort of gts by x1 ----------------
__global__ void k_gtsort(const float* __restrict__ gt) {
    __shared__ unsigned long long key[1024];
    __shared__ float swm[1024];
    int c = blockIdx.x, t = threadIdx.x;
    float w = 0.0f;
    if (t < NG) {
        const float* gp = gt + ((size_t)c * NG + t) * 7;
        float x1 = gp[3];
        key[t] = ((unsigned long long)__float_as_uint(x1) << 32) | (unsigned int)t;
        w = gp[5] - x1;
    } else {
        key[t] = 0xFFFFFFFFFFFFFFFFULL;
    }
    swm[t] = w;
    __syncthreads();
    for (int k2 = 2; k2 <= 1024; k2 <<= 1) {
        for (int j = k2 >> 1; j > 0; j >>= 1) {
            int ixj = t ^ j;
            if (ixj > t) {
                bool up = ((t & k2) == 0);
                unsigned long long a = key[t], b = key[ixj];
                if ((a > b) == up) { key[t] = b; key[ixj] = a; }
            }
            __syncthreads();
        }
    }
    for (int s = 512; s > 0; s >>= 1) {
        if (t < s) swm[t] = fmaxf(swm[t], swm[t + s]);
        __syncthreads();
    }
    if (t == 0) g_gwmax[c] = swm[0];
    if (t < NG) {
        int oi = (int)(key[t] & 0xffffffffULL);
        const float* gp = gt + ((size_t)c * NG + oi) * 7;
        float x1 = gp[3], y1 = gp[4], x2 = gp[5], y2 = gp[6];
        int o = c * NG + t;
        g_sgbox[o]  = make_float4(x1, y1, x2, y2);
        g_sgarea[o] = (x2 - x1) * (y2 - y1);
        g_sgidx[o]  = oi;
        g_sgx1[o]   = x1;
    }
}

// ---------------- K5: match — x-sorted preds, 2 per thread, windowed gts ----------------
#define MB 256                 // threads per block
#define PPB (2 * MB)           // preds per block
__global__ void __launch_bounds__(MB) k_match() {
    __shared__ float4 sg[NG];
    __shared__ float  sa[NG];
    __shared__ int    si[NG];
    __shared__ float  sx[NG];
    __shared__ float  s_wmax;
    int c = blockIdx.y;
    for (int g = threadIdx.x; g < NG; g += MB) {
        int o = c * NG + g;
        sg[g] = g_sgbox[o];
        sa[g] = g_sgarea[o];
        si[g] = g_sgidx[o];
        sx[g] = g_sgx1[o];
    }
    if (threadIdx.x == 0) s_wmax = g_gwmax[c];
    __syncthreads();

    int j0 = blockIdx.x * PPB + threadIdx.x;   // sorted-order indices
    int j1 = j0 + MB;
    if (j0 >= NP) return;
    bool v1 = j1 < NP;

    size_t cb = (size_t)c * NP;
    float4 A = g_pbox[cb + j0];
    float4 B = g_pbox[cb + (v1 ? j1 : j0)];
    float areaA = (A.z - A.x) * (A.w - A.y);
    float areaB = (B.z - B.x) * (B.w - B.y);

    // union candidate window: gx1 in [min(ax1,bx1)-wmax, max(ax2,bx2))
    float loval = fminf(A.x, B.x) - s_wmax;
    float hival = fmaxf(A.z, B.z);
    int lo = 0;
    {
        int n = NG;
        while (n > 0) {
            int half = n >> 1, mid = lo + half;
            if (sx[mid] < loval) { lo = mid + 1; n -= half + 1; }
            else n = half;
        }
    }
    int hi;
    {
        int b = lo, n = NG - lo;
        while (n > 0) {
            int half = n >> 1, mid = b + half;
            if (sx[mid] < hival) { b = mid + 1; n -= half + 1; }
            else n = half;
        }
        hi = b;
    }

    float ai = 0.0f, ad = 1.0f; int agi = 0x7fffffff;
    float bi = 0.0f, bd = 1.0f; int bgi = 0x7fffffff;
#pragma unroll 4
    for (int g = lo; g < hi; g++) {
        float4 q = sg[g];
        float ga = sa[g];
        int   gi = si[g];

        float w0 = fminf(A.z, q.z) - fmaxf(A.x, q.x);
        float h0 = fminf(A.w, q.w) - fmaxf(A.y, q.y);
        w0 = fmaxf(w0, 0.0f); h0 = fmaxf(h0, 0.0f);
        float i0 = w0 * h0;
        float d0 = areaA + ga - i0;
        float l0 = i0 * ad, r0 = ai * d0;
        if (l0 > r0 || (l0 == r0 && gi < agi)) { ai = i0; ad = d0; agi = gi; }

        float w1 = fminf(B.z, q.z) - fmaxf(B.x, q.x);
        float h1 = fminf(B.w, q.w) - fmaxf(B.y, q.y);
        w1 = fmaxf(w1, 0.0f); h1 = fmaxf(h1, 0.0f);
        float i1 = w1 * h1;
        float d1 = areaB + ga - i1;
        float l1 = i1 * bd, r1 = bi * d1;
        if (l1 > r1 || (l1 == r1 && gi < bgi)) { bi = i1; bd = d1; bgi = gi; }
    }

    {
        int op = g_pidx[c * NP + j0];
        int idx = c * NP + op;
        float iou = ai / (ad + 1e-9f);
        if (iou > 0.5f) {
            g_match[idx] = agi;
            atomicMin(&g_first[c * NG + agi], g_rank[idx]);
        } else {
            g_match[idx] = -1;
        }
    }
    if (v1) {
        int op = g_pidx[c * NP + j1];
        int idx = c * NP + op;
        float iou = bi / (bd + 1e-9f);
        if (iou > 0.5f) {
            g_match[idx] = bgi;
            atomicMin(&g_first[c * NG + bgi], g_rank[idx]);
        } else {
            g_match[idx] = -1;
        }
    }
}

// ---------------- K6: collect true positives ----------------
__global__ void k_tp() {
    int i = blockIdx.x * blockDim.x + threadIdx.x;
    if (i >= NC * NP) return;
    int m = g_match[i];
    if (m < 0) return;
    int c = i / NP;
    int r = g_rank[i];
    if (g_first[c * NG + m] == r) {
        int t = atomicAdd(&g_tpcnt[c], 1);
        g_tprank[c * 1024 + t] = r;
    }
}

// ---------------- K7: per-class AP ----------------
__global__ void k_ap() {
    __shared__ int    sr[1024];
    __shared__ double red[1024];
    int c = blockIdx.x, t = threadIdx.x;
    int n = g_tpcnt[c];
    sr[t] = (t < n) ? g_tprank[c * 1024 + t] : 0x7fffffff;
    __syncthreads();
    double term = 0.0;
    if (t < n) {
        int r = sr[t];
        int cnt = 1;
        for (int j = 0; j < n; j++) cnt += (sr[j] < r) ? 1 : 0;
        if (r > 0) {
            float p1 = (float)cnt / (float)(r + 1);
            float p0 = (float)(cnt - 1) / (float)r;
            term = 0.5 * ((double)p1 + (double)p0);
        }
    }
    red[t] = term;
    __syncthreads();
    for (int s = 512; s > 0; s >>= 1) {
        if (t < s) red[t] += red[t + s];
        __syncthreads();
    }
    if (t == 0) g_ap[c] = (float)(red[0] / (double)NG);
}

// ---------------- K8: mean over classes ----------------
__global__ void k_mean(float* __restrict__ out) {
    __shared__ double red[128];
    int t = threadIdx.x;
    red[t] = (t < NC) ? (double)g_ap[t] : 0.0;
    __syncthreads();
    for (int s = 64; s > 0; s >>= 1) {
        if (t < s) red[t] += red[t + s];
        __syncthreads();
    }
    if (t == 0) out[0] = (float)(red[0] / (double)NC);
}

// ---------------- launcher ----------------
extern "C" void kernel_launch(void* const* d_in, const int* in_sizes, int n_in,
                              void* d_out, int out_size) {
    const float* pred;
    const float* gt;
    if (in_sizes[0] == NC * NP * 7) { pred = (const float*)d_in[0]; gt = (const float*)d_in[1]; }
    else                            { pred = (const float*)d_in[1]; gt = (const float*)d_in[0]; }

    const int NTOT = NC * NP;
    k_init<<<(NC * NB + 255) / 256, 256>>>();
    k_hist<<<(NTOT + 255) / 256, 256>>>(pred);
    k_scan<<<NC, 1024>>>();
    k_xscan<<<NC, NXB>>>();
    k_scatter<<<(NTOT + 255) / 256, 256>>>();
    k_xscatter<<<(NTOT + 255) / 256, 256>>>(pred);
    k_bsort<<<(NC * NB + 255) / 256, 256>>>();
    k_gtsort<<<NC, 1024>>>(gt);
    dim3 mg((NP + PPB - 1) / PPB, NC);
    k_match<<<mg, MB>>>();
    k_tp<<<(NTOT + 255) / 256, 256>>>();
    k_ap<<<NC, 1024>>>();
    k_mean<<<1, 128>>>((float*)d_out);
}

// round 6
// speedup vs baseline: 2.2392x; 1.2973x over previous
#include <cuda_runtime.h>
#include <stdint.h>

#define NC 80
#define NP 30000
#define NG 800
#define NB 16384   // score buckets (2^14)
#define NXB 256    // x-position buckets for pred locality sort

// ---------------- scratch (static device globals; no allocation) ----------------
__device__ unsigned long long g_slot[(size_t)NC * NP];
__device__ int   g_rank[NC * NP];
__device__ int   g_match[NC * NP];
__device__ unsigned int g_sbits[NC * NP];
__device__ int   g_hist[NC * NB];
__device__ int   g_base[NC * NB];
__device__ int   g_cursor[NC * NB];
__device__ int   g_xhist[NC * NXB];
__device__ int   g_xcursor[NC * NXB];
__device__ int   g_first[NC * NG];
__device__ int   g_tpcnt[NC];
__device__ int   g_tprank[NC * 1024];
__device__ float g_ap[NC];
// compact boxes in input order (stashed by k_prep)
__device__ float4 g_pboxin[(size_t)NC * NP];
// preds sorted by x-bucket
__device__ float4 g_pbox[(size_t)NC * NP];
__device__ int    g_pidx[NC * NP];
// gts sorted by x1
__device__ float4 g_sgbox[NC * NG];
__device__ float  g_sgarea[NC * NG];
__device__ int    g_sgidx[NC * NG];
__device__ float  g_sgx1[NC * NG];
__device__ float  g_gwmax[NC];

// ---------------- K0: init ----------------
__global__ void k_init() {
    int i = blockIdx.x * blockDim.x + threadIdx.x;
    if (i < NC * NB)  g_hist[i] = 0;
    if (i < NC * NXB) g_xhist[i] = 0;
    if (i < NC * NG)  g_first[i] = NP;
    if (i < NC)       g_tpcnt[i] = 0;
}

__device__ __forceinline__ int xbucket(float x1) {
    int b = (int)(x1 * (1.0f / 1024.0f) * (float)NXB);
    return max(0, min(b, NXB - 1));
}

// ---------------- K1: histograms + stash compact boxes (single pred pass) ----------------
__global__ void k_prep(const float* __restrict__ pred) {
    int i = blockIdx.x * blockDim.x + threadIdx.x;
    if (i >= NC * NP) return;
    const float* pp = pred + (size_t)i * 7;
    float s  = pp[2];
    float x1 = pp[3], y1 = pp[4], x2 = pp[5], y2 = pp[6];
    g_sbits[i]  = __float_as_uint(s);
    g_pboxin[i] = make_float4(x1, y1, x2, y2);
    int b = (int)(s * 16384.0f);
    b = max(0, min(b, NB - 1));
    int c = i / NP;
    atomicAdd(&g_hist[c * NB + b], 1);
    atomicAdd(&g_xhist[c * NXB + xbucket(x1)], 1);
}

// ---------------- K2: per-class suffix scan of score buckets ----------------
__global__ void k_scan() {
    __shared__ int ssum[1024];
    int c = blockIdx.x, t = threadIdx.x;
    int h[16], tot = 0;
    int off0 = c * NB + t * 16;
#pragma unroll
    for (int j = 0; j < 16; j++) { h[j] = g_hist[off0 + j]; tot += h[j]; }
    ssum[t] = tot;
    __syncthreads();
    for (int off = 1; off < 1024; off <<= 1) {
        int v = (t + off < 1024) ? ssum[t + off] : 0;
        __syncthreads();
        ssum[t] += v;
        __syncthreads();
    }
    int running = ssum[t] - tot;
#pragma unroll
    for (int j = 15; j >= 0; j--) {
        g_base[off0 + j]   = running;
        g_cursor[off0 + j] = running;
        running += h[j];
    }
}

// ---------------- K2b: per-class ascending exclusive scan of x buckets ----------------
__global__ void k_xscan() {
    __shared__ int sh[NXB];
    int c = blockIdx.x, t = threadIdx.x;
    sh[t] = g_xhist[c * NXB + t];
    __syncthreads();
    int v = sh[t];
    for (int off = 1; off < NXB; off <<= 1) {
        int u = (t >= off) ? sh[t - off] : 0;
        __syncthreads();
        sh[t] += u;
        __syncthreads();
    }
    g_xcursor[c * NXB + t] = sh[t] - v;   // exclusive prefix
}

// ---------------- K3: scatter score slots ----------------
__global__ void k_scatter() {
    int i = blockIdx.x * blockDim.x + threadIdx.x;
    if (i >= NC * NP) return;
    unsigned int sb = g_sbits[i];
    float s = __uint_as_float(sb);
    int b = (int)(s * 16384.0f);
    b = max(0, min(b, NB - 1));
    int c = i / NP, p = i - c * NP;
    int slot = atomicAdd(&g_cursor[c * NB + b], 1);
    g_slot[(size_t)c * NP + slot] = ((unsigned long long)(~sb) << 32) | (unsigned int)p;
}

// ---------------- K3b: scatter preds into x-sorted order (compact source) ----------------
__global__ void k_xscatter() {
    int i = blockIdx.x * blockDim.x + threadIdx.x;
    if (i >= NC * NP) return;
    float4 bx = g_pboxin[i];
    int c = i / NP, p = i - c * NP;
    int slot = atomicAdd(&g_xcursor[c * NXB + xbucket(bx.x)], 1);
    g_pbox[(size_t)c * NP + slot] = bx;
    g_pidx[c * NP + slot] = p;
}

// ---------------- K4: per-bucket insertion sort + ranks ----------------
__global__ void k_bsort() {
    int i = blockIdx.x * blockDim.x + threadIdx.x;
    if (i >= NC * NB) return;
    int m = g_hist[i];
    if (m == 0) return;
    int c = i / NB;
    int base = g_base[i];
    unsigned long long* s = g_slot + (size_t)c * NP + base;
    for (int a = 1; a < m; a++) {
        unsigned long long k = s[a];
        int j = a - 1;
        while (j >= 0 && s[j] > k) { s[j + 1] = s[j]; j--; }
        s[j + 1] = k;
    }
    for (int t = 0; t < m; t++) {
        int idx = (int)(s[t] & 0xffffffffULL);
        g_rank[c * NP + idx] = base + t;
    }
}

// ---------------- K4b: per-class bitonic sort of gts by x1 ----------------
__global__ void k_gtsort(const float* __restrict__ gt) {
    __shared__ unsigned long long key[1024];
    __shared__ float swm[1024];
    int c = blockIdx.x, t = threadIdx.x;
    float w = 0.0f;
    if (t < NG) {
        const float* gp = gt + ((size_t)c * NG + t) * 7;
        float x1 = gp[3];
        key[t] = ((unsigned long long)__float_as_uint(x1) << 32) | (unsigned int)t;
        w = gp[5] - x1;
    } else {
        key[t] = 0xFFFFFFFFFFFFFFFFULL;
    }
    swm[t] = w;
    __syncthreads();
    for (int k2 = 2; k2 <= 1024; k2 <<= 1) {
        for (int j = k2 >> 1; j > 0; j >>= 1) {
            int ixj = t ^ j;
            if (ixj > t) {
                bool up = ((t & k2) == 0);
                unsigned long long a = key[t], b = key[ixj];
                if ((a > b) == up) { key[t] = b; key[ixj] = a; }
            }
            __syncthreads();
        }
    }
    for (int s = 512; s > 0; s >>= 1) {
        if (t < s) swm[t] = fmaxf(swm[t], swm[t + s]);
        __syncthreads();
    }
    if (t == 0) g_gwmax[c] = swm[0];
    if (t < NG) {
        int oi = (int)(key[t] & 0xffffffffULL);
        const float* gp = gt + ((size_t)c * NG + oi) * 7;
        float x1 = gp[3], y1 = gp[4], x2 = gp[5], y2 = gp[6];
        int o = c * NG + t;
        g_sgbox[o]  = make_float4(x1, y1, x2, y2);
        g_sgarea[o] = (x2 - x1) * (y2 - y1);
        g_sgidx[o]  = oi;
        g_sgx1[o]   = x1;
    }
}

// ---------------- K5: match — tightened window (valid-winner bound) ----------------
#define MB 256                 // threads per block
#define PPB (2 * MB)           // preds per block
#define SLACK 0.25f
__global__ void __launch_bounds__(MB) k_match() {
    __shared__ float4 sg[NG];
    __shared__ float  sa[NG];
    __shared__ int    si[NG];
    __shared__ float  sx[NG];
    __shared__ float  s_wmax;
    int c = blockIdx.y;
    for (int g = threadIdx.x; g < NG; g += MB) {
        int o = c * NG + g;
        sg[g] = g_sgbox[o];
        sa[g] = g_sgarea[o];
        si[g] = g_sgidx[o];
        sx[g] = g_sgx1[o];
    }
    if (threadIdx.x == 0) s_wmax = g_gwmax[c];
    __syncthreads();

    int j0 = blockIdx.x * PPB + threadIdx.x;   // sorted-order indices
    int j1 = j0 + MB;
    if (j0 >= NP) return;
    bool v1 = j1 < NP;

    size_t cb = (size_t)c * NP;
    float4 A = g_pbox[cb + j0];
    float4 B = g_pbox[cb + (v1 ? j1 : j0)];
    float areaA = (A.z - A.x) * (A.w - A.y);
    float areaB = (B.z - B.x) * (B.w - B.y);
    float sumA0 = areaA;   // areaA + ga computed per-iter
    float sumB0 = areaB;

    // Tight window: a gt can only be the VALID (iou>0.5) winner if its
    // x-overlap with the pred exceeds wA/3  =>  gx1 in
    // [ax1 + wA/3 - wmax, ax2 - wA/3]  (slack >> ulp noise).
    float wA3 = (A.z - A.x) * (1.0f / 3.0f);
    float wB3 = (B.z - B.x) * (1.0f / 3.0f);
    float loA = A.x + wA3 - s_wmax, hiA = A.z - wA3;
    float loB = B.x + wB3 - s_wmax, hiB = B.z - wB3;
    float loval = fminf(loA, loB) - SLACK;
    float hival = fmaxf(hiA, hiB) + SLACK;

    int lo = 0;
    {
        int n = NG;
        while (n > 0) {
            int half = n >> 1, mid = lo + half;
            if (sx[mid] < loval) { lo = mid + 1; n -= half + 1; }
            else n = half;
        }
    }
    int hi;
    {
        int b = lo, n = NG - lo;
        while (n > 0) {
            int half = n >> 1, mid = b + half;
            if (sx[mid] < hival) { b = mid + 1; n -= half + 1; }
            else n = half;
        }
        hi = b;
    }

    float ai = 0.0f, ad = 1.0f; int ag = 0;   // winner tracked by SORTED index
    float bi = 0.0f, bd = 1.0f; int bg = 0;
#pragma unroll 4
    for (int g = lo; g < hi; g++) {
        float4 q = sg[g];
        float ga = sa[g];

        float w0 = fminf(A.z, q.z) - fmaxf(A.x, q.x);
        float h0 = fminf(A.w, q.w) - fmaxf(A.y, q.y);
        float i0 = fmaxf(w0, 0.0f) * fmaxf(h0, 0.0f);
        float d0 = (sumA0 + ga) - i0;
        if (i0 * ad > ai * d0) { ai = i0; ad = d0; ag = g; }

        float w1 = fminf(B.z, q.z) - fmaxf(B.x, q.x);
        float h1 = fminf(B.w, q.w) - fmaxf(B.y, q.y);
        float i1 = fmaxf(w1, 0.0f) * fmaxf(h1, 0.0f);
        float d1 = (sumB0 + ga) - i1;
        if (i1 * bd > bi * d1) { bi = i1; bd = d1; bg = g; }
    }

    {
        int op = g_pidx[c * NP + j0];
        int idx = c * NP + op;
        float iou = ai / (ad + 1e-9f);
        if (iou > 0.5f) {
            int agi = si[ag];
            g_match[idx] = agi;
            atomicMin(&g_first[c * NG + agi], g_rank[idx]);
        } else {
            g_match[idx] = -1;
        }
    }
    if (v1) {
        int op = g_pidx[c * NP + j1];
        int idx = c * NP + op;
        float iou = bi / (bd + 1e-9f);
        if (iou > 0.5f) {
            int bgi = si[bg];
            g_match[idx] = bgi;
            atomicMin(&g_first[c * NG + bgi], g_rank[idx]);
        } else {
            g_match[idx] = -1;
        }
    }
}

// ---------------- K6: collect true positives ----------------
__global__ void k_tp() {
    int i = blockIdx.x * blockDim.x + threadIdx.x;
    if (i >= NC * NP) return;
    int m = g_match[i];
    if (m < 0) return;
    int c = i / NP;
    int r = g_rank[i];
    if (g_first[c * NG + m] == r) {
        int t = atomicAdd(&g_tpcnt[c], 1);
        g_tprank[c * 1024 + t] = r;
    }
}

// ---------------- K7: per-class AP ----------------
__global__ void k_ap() {
    __shared__ int    sr[1024];
    __shared__ double red[1024];
    int c = blockIdx.x, t = threadIdx.x;
    int n = g_tpcnt[c];
    sr[t] = (t < n) ? g_tprank[c * 1024 + t] : 0x7fffffff;
    __syncthreads();
    double term = 0.0;
    if (t < n) {
        int r = sr[t];
        int cnt = 1;
        for (int j = 0; j < n; j++) cnt += (sr[j] < r) ? 1 : 0;
        if (r > 0) {
            float p1 = (float)cnt / (float)(r + 1);
            float p0 = (float)(cnt - 1) / (float)r;
            term = 0.5 * ((double)p1 + (double)p0);
        }
    }
    red[t] = term;
    __syncthreads();
    for (int s = 512; s > 0; s >>= 1) {
        if (t < s) red[t] += red[t + s];
        __syncthreads();
    }
    if (t == 0) g_ap[c] = (float)(red[0] / (double)NG);
}

// ---------------- K8: mean over classes ----------------
__global__ void k_mean(float* __restrict__ out) {
    __shared__ double red[128];
    int t = threadIdx.x;
    red[t] = (t < NC) ? (double)g_ap[t] : 0.0;
    __syncthreads();
    for (int s = 64; s > 0; s >>= 1) {
        if (t < s) red[t] += red[t + s];
        __syncthreads();
    }
    if (t == 0) out[0] = (float)(red[0] / (double)NC);
}

// ---------------- launcher ----------------
extern "C" void kernel_launch(void* const* d_in, const int* in_sizes, int n_in,
                              void* d_out, int out_size) {
    const float* pred;
    const float* gt;
    if (in_sizes[0] == NC * NP * 7) { pred = (const float*)d_in[0]; gt = (const float*)d_in[1]; }
    else                            { pred = (const float*)d_in[1]; gt = (const float*)d_in[0]; }

    const int NTOT = NC * NP;
    k_init<<<(NC * NB + 255) / 256, 256>>>();
    k_prep<<<(NTOT + 255) / 256, 256>>>(pred);
    k_scan<<<NC, 1024>>>();
    k_xscan<<<NC, NXB>>>();
    k_scatter<<<(NTOT + 255) / 256, 256>>>();
    k_xscatter<<<(NTOT + 255) / 256, 256>>>();
    k_bsort<<<(NC * NB + 255) / 256, 256>>>();
    k_gtsort<<<NC, 1024>>>(gt);
    dim3 mg((NP + PPB - 1) / PPB, NC);
    k_match<<<mg, MB>>>();
    k_tp<<<(NTOT + 255) / 256, 256>>>();
    k_ap<<<NC, 1024>>>();
    k_mean<<<1, 128>>>((float*)d_out);
}

// round 7
// speedup vs baseline: 2.6174x; 1.1689x over previous
#include <cuda_runtime.h>
#include <stdint.h>

#define NC 80
#define NP 30000
#define NG 800
#define NB 16384      // score buckets (2^14)
#define NXB 256       // x-position buckets
#define NWB 4         // width sub-buckets
#define NXBIN (NXB * NWB)

// ---------------- scratch (static device globals; no allocation) ----------------
__device__ unsigned long long g_slot[(size_t)NC * NP];   // (score_bits<<32)|idx, unsorted per bucket
__device__ unsigned int g_sbits[NC * NP];
__device__ int   g_hist[NC * NB];
__device__ int   g_base[NC * NB];
__device__ int   g_cursor[NC * NB];
__device__ int   g_xhist[NC * NXBIN];
__device__ int   g_xcursor[NC * NXBIN];
__device__ unsigned long long g_best[NC * NG];  // per-gt winner: (score<<32)|~idx
__device__ int   g_tpcnt[NC];
__device__ int   g_tprank[NC * 1024];
__device__ float g_ap[NC];
// compact boxes in input order
__device__ float4 g_pboxin[(size_t)NC * NP];
// preds sorted by (x-bucket, width-bucket)
__device__ float4 g_pbox[(size_t)NC * NP];
__device__ int    g_pidx[NC * NP];
__device__ unsigned int g_pscore[NC * NP];
// gts sorted by x1
__device__ float4 g_sgbox[NC * NG];
__device__ float  g_sgarea[NC * NG];
__device__ int    g_sgidx[NC * NG];
__device__ float  g_sgx1[NC * NG];
__device__ float  g_gwmax[NC];

__device__ __forceinline__ int xbucket(float x1) {
    int b = (int)(x1 * ((float)NXB / 1024.0f));
    return max(0, min(b, NXB - 1));
}
__device__ __forceinline__ int wbucket(float w) {
    int b = (int)((w - 4.0f) * (1.0f / 31.0f));
    return max(0, min(b, NWB - 1));
}
__device__ __forceinline__ int sbucket(float s) {
    int b = (int)(s * 16384.0f);
    return max(0, min(b, NB - 1));
}

// ---------------- K0: init ----------------
__global__ void k_init() {
    int i = blockIdx.x * blockDim.x + threadIdx.x;
    if (i < NC * NB)   g_hist[i] = 0;
    if (i < NC * NXBIN) g_xhist[i] = 0;
    if (i < NC * NG)   g_best[i] = 0ULL;
    if (i < NC)        g_tpcnt[i] = 0;
}

// ---------------- K1: histograms + stash compact boxes (single pred pass) ----------------
__global__ void k_prep(const float* __restrict__ pred) {
    int i = blockIdx.x * blockDim.x + threadIdx.x;
    if (i >= NC * NP) return;
    const float* pp = pred + (size_t)i * 7;
    float s  = pp[2];
    float x1 = pp[3], y1 = pp[4], x2 = pp[5], y2 = pp[6];
    g_sbits[i]  = __float_as_uint(s);
    g_pboxin[i] = make_float4(x1, y1, x2, y2);
    int c = i / NP;
    atomicAdd(&g_hist[c * NB + sbucket(s)], 1);
    atomicAdd(&g_xhist[c * NXBIN + xbucket(x1) * NWB + wbucket(x2 - x1)], 1);
}

// ---------------- K2: per-class suffix-exclusive scan of score buckets ----------------
__global__ void k_scan() {
    __shared__ int ssum[1024];
    int c = blockIdx.x, t = threadIdx.x;
    int h[16], tot = 0;
    int off0 = c * NB + t * 16;
#pragma unroll
    for (int j = 0; j < 16; j++) { h[j] = g_hist[off0 + j]; tot += h[j]; }
    ssum[t] = tot;
    __syncthreads();
    for (int off = 1; off < 1024; off <<= 1) {
        int v = (t + off < 1024) ? ssum[t + off] : 0;
        __syncthreads();
        ssum[t] += v;
        __syncthreads();
    }
    int running = ssum[t] - tot;
#pragma unroll
    for (int j = 15; j >= 0; j--) {
        g_base[off0 + j]   = running;
        g_cursor[off0 + j] = running;
        running += h[j];
    }
}

// ---------------- K2b: per-class ascending exclusive scan of x bins ----------------
__global__ void k_xscan() {
    __shared__ int sh[NXBIN];
    int c = blockIdx.x, t = threadIdx.x;
    sh[t] = g_xhist[c * NXBIN + t];
    __syncthreads();
    int v = sh[t];
    for (int off = 1; off < NXBIN; off <<= 1) {
        int u = (t >= off) ? sh[t - off] : 0;
        __syncthreads();
        sh[t] += u;
        __syncthreads();
    }
    g_xcursor[c * NXBIN + t] = sh[t] - v;   // exclusive prefix
}

// ---------------- K3: fused scatter (score slots + x-sorted preds) ----------------
__global__ void k_fscatter() {
    int i = blockIdx.x * blockDim.x + threadIdx.x;
    if (i >= NC * NP) return;
    int c = i / NP, p = i - c * NP;
    unsigned int sb = g_sbits[i];
    float s = __uint_as_float(sb);
    int slot = atomicAdd(&g_cursor[c * NB + sbucket(s)], 1);
    g_slot[(size_t)c * NP + slot] = ((unsigned long long)sb << 32) | (unsigned int)p;

    float4 bx = g_pboxin[i];
    int bin = xbucket(bx.x) * NWB + wbucket(bx.z - bx.x);
    int xs = atomicAdd(&g_xcursor[c * NXBIN + bin], 1);
    size_t o = (size_t)c * NP + xs;
    g_pbox[o] = bx;
    g_pidx[c * NP + xs] = p;
    g_pscore[c * NP + xs] = sb;
}

// ---------------- K4: per-class bitonic sort of gts by x1 ----------------
__global__ void k_gtsort(const float* __restrict__ gt) {
    __shared__ unsigned long long key[1024];
    __shared__ float swm[1024];
    int c = blockIdx.x, t = threadIdx.x;
    float w = 0.0f;
    if (t < NG) {
        const float* gp = gt + ((size_t)c * NG + t) * 7;
        float x1 = gp[3];
        key[t] = ((unsigned long long)__float_as_uint(x1) << 32) | (unsigned int)t;
        w = gp[5] - x1;
    } else {
        key[t] = 0xFFFFFFFFFFFFFFFFULL;
    }
    swm[t] = w;
    __syncthreads();
    for (int k2 = 2; k2 <= 1024; k2 <<= 1) {
        for (int j = k2 >> 1; j > 0; j >>= 1) {
            int ixj = t ^ j;
            if (ixj > t) {
                bool up = ((t & k2) == 0);
                unsigned long long a = key[t], b = key[ixj];
                if ((a > b) == up) { key[t] = b; key[ixj] = a; }
            }
            __syncthreads();
        }
    }
    for (int s = 512; s > 0; s >>= 1) {
        if (t < s) swm[t] = fmaxf(swm[t], swm[t + s]);
        __syncthreads();
    }
    if (t == 0) g_gwmax[c] = swm[0];
    if (t < NG) {
        int oi = (int)(key[t] & 0xffffffffULL);
        const float* gp = gt + ((size_t)c * NG + oi) * 7;
        float x1 = gp[3], y1 = gp[4], x2 = gp[5], y2 = gp[6];
        int o = c * NG + t;
        g_sgbox[o]  = make_float4(x1, y1, x2, y2);
        g_sgarea[o] = (x2 - x1) * (y2 - y1);
        g_sgidx[o]  = oi;
        g_sgx1[o]   = x1;
    }
}

// ---------------- K5: match — winner via 64-bit atomicMax keyed by score ----------------
#define MB 256
#define PPB (2 * MB)
#define SLACK 0.25f
__global__ void __launch_bounds__(MB) k_match() {
    __shared__ float4 sg[NG];
    __shared__ float  sa[NG];
    __shared__ int    si[NG];
    __shared__ float  sx[NG];
    __shared__ float  s_wmax;
    int c = blockIdx.y;
    for (int g = threadIdx.x; g < NG; g += MB) {
        int o = c * NG + g;
        sg[g] = g_sgbox[o];
        sa[g] = g_sgarea[o];
        si[g] = g_sgidx[o];
        sx[g] = g_sgx1[o];
    }
    if (threadIdx.x == 0) s_wmax = g_gwmax[c];
    __syncthreads();

    int j0 = blockIdx.x * PPB + threadIdx.x;
    int j1 = j0 + MB;
    if (j0 >= NP) return;
    bool v1 = j1 < NP;

    size_t cb = (size_t)c * NP;
    float4 A = g_pbox[cb + j0];
    float4 B = g_pbox[cb + (v1 ? j1 : j0)];
    float areaA = (A.z - A.x) * (A.w - A.y);
    float areaB = (B.z - B.x) * (B.w - B.y);

    // valid-winner window: gx1 in [ax1 + wA/3 - wmax, ax2 - wA/3] (+slack)
    float wA3 = (A.z - A.x) * (1.0f / 3.0f);
    float wB3 = (B.z - B.x) * (1.0f / 3.0f);
    float loval = fminf(A.x + wA3, B.x + wB3) - s_wmax - SLACK;
    float hival = fmaxf(A.z - wA3, B.z - wB3) + SLACK;

    int lo = 0;
    {
        int n = NG;
        while (n > 0) {
            int half = n >> 1, mid = lo + half;
            if (sx[mid] < loval) { lo = mid + 1; n -= half + 1; }
            else n = half;
        }
    }
    int hi;
    {
        int b = lo, n = NG - lo;
        while (n > 0) {
            int half = n >> 1, mid = b + half;
            if (sx[mid] < hival) { b = mid + 1; n -= half + 1; }
            else n = half;
        }
        hi = b;
    }

    float ai = 0.0f, ad = 1.0f; int ag = 0;
    float bi = 0.0f, bd = 1.0f; int bg = 0;
#pragma unroll 4
    for (int g = lo; g < hi; g++) {
        float4 q = sg[g];
        float ga = sa[g];

        float w0 = fminf(A.z, q.z) - fmaxf(A.x, q.x);
        float h0 = fminf(A.w, q.w) - fmaxf(A.y, q.y);
        float i0 = fmaxf(w0, 0.0f) * fmaxf(h0, 0.0f);
        float d0 = (areaA + ga) - i0;
        if (i0 * ad > ai * d0) { ai = i0; ad = d0; ag = g; }

        float w1 = fminf(B.z, q.z) - fmaxf(B.x, q.x);
        float h1 = fminf(B.w, q.w) - fmaxf(B.y, q.y);
        float i1 = fmaxf(w1, 0.0f) * fmaxf(h1, 0.0f);
        float d1 = (areaB + ga) - i1;
        if (i1 * bd > bi * d1) { bi = i1; bd = d1; bg = g; }
    }

    {
        float iou = ai / (ad + 1e-9f);
        if (iou > 0.5f) {
            int agi = si[ag];
            unsigned int op = (unsigned int)g_pidx[c * NP + j0];
            unsigned long long key =
                ((unsigned long long)g_pscore[c * NP + j0] << 32) | (unsigned int)(~op);
            atomicMax(&g_best[c * NG + agi], key);
        }
    }
    if (v1) {
        float iou = bi / (bd + 1e-9f);
        if (iou > 0.5f) {
            int bgi = si[bg];
            unsigned int op = (unsigned int)g_pidx[c * NP + j1];
            unsigned long long key =
                ((unsigned long long)g_pscore[c * NP + j1] << 32) | (unsigned int)(~op);
            atomicMax(&g_best[c * NG + bgi], key);
        }
    }
}

// ---------------- K6: per-gt winner -> global rank (bucket count) ----------------
__global__ void k_collect() {
    int i = blockIdx.x * blockDim.x + threadIdx.x;
    if (i >= NC * NG) return;
    unsigned long long key = g_best[i];
    if (key == 0ULL) return;
    unsigned int sb = (unsigned int)(key >> 32);
    unsigned int op = ~((unsigned int)key);
    int c = i / NG;
    int b = sbucket(__uint_as_float(sb));
    int base = g_base[c * NB + b];
    int cnt  = g_hist[c * NB + b];
    const unsigned long long* s = g_slot + (size_t)c * NP + base;
    int better = 0;
    for (int k = 0; k < cnt; k++) {
        unsigned long long e = s[k];
        unsigned int qs = (unsigned int)(e >> 32);
        unsigned int qp = (unsigned int)e;
        better += (qs > sb) || (qs == sb && qp < op);
    }
    int rank = base + better;
    int t = atomicAdd(&g_tpcnt[c], 1);
    g_tprank[c * 1024 + t] = rank;
}

// ---------------- K7: per-class AP ----------------
__global__ void k_ap() {
    __shared__ int    sr[1024];
    __shared__ double red[1024];
    int c = blockIdx.x, t = threadIdx.x;
    int n = g_tpcnt[c];
    sr[t] = (t < n) ? g_tprank[c * 1024 + t] : 0x7fffffff;
    __syncthreads();
    double term = 0.0;
    if (t < n) {
        int r = sr[t];
        int cnt = 1;
        for (int j = 0; j < n; j++) cnt += (sr[j] < r) ? 1 : 0;
        if (r > 0) {
            float p1 = (float)cnt / (float)(r + 1);
            float p0 = (float)(cnt - 1) / (float)r;
            term = 0.5 * ((double)p1 + (double)p0);
        }
    }
    red[t] = term;
    __syncthreads();
    for (int s = 512; s > 0; s >>= 1) {
        if (t < s) red[t] += red[t + s];
        __syncthreads();
    }
    if (t == 0) g_ap[c] = (float)(red[0] / (double)NG);
}

// ---------------- K8: mean over classes ----------------
__global__ void k_mean(float* __restrict__ out) {
    __shared__ double red[128];
    int t = threadIdx.x;
    red[t] = (t < NC) ? (double)g_ap[t] : 0.0;
    __syncthreads();
    for (int s = 64; s > 0; s >>= 1) {
        if (t < s) red[t] += red[t + s];
        __syncthreads();
    }
    if (t == 0) out[0] = (float)(red[0] / (double)NC);
}

// ---------------- launcher ----------------
extern "C" void kernel_launch(void* const* d_in, const int* in_sizes, int n_in,
                              void* d_out, int out_size) {
    const float* pred;
    const float* gt;
    if (in_sizes[0] == NC * NP * 7) { pred = (const float*)d_in[0]; gt = (const float*)d_in[1]; }
    else                            { pred = (const float*)d_in[1]; gt = (const float*)d_in[0]; }

    const int NTOT = NC * NP;
    k_init<<<(NC * NB + 255) / 256, 256>>>();
    k_prep<<<(NTOT + 255) / 256, 256>>>(pred);
    k_scan<<<NC, 1024>>>();
    k_xscan<<<NC, NXBIN>>>();
    k_fscatter<<<(NTOT + 255) / 256, 256>>>();
    k_gtsort<<<NC, 1024>>>(gt);
    dim3 mg((NP + PPB - 1) / PPB, NC);
    k_match<<<mg, MB>>>();
    k_collect<<<(NC * NG + 255) / 256, 256>>>();
    k_ap<<<NC, 1024>>>();
    k_mean<<<1, 128>>>((float*)d_out);
}

// round 9
// speedup vs baseline: 3.1068x; 1.1870x over previous
#include <cuda_runtime.h>
#include <stdint.h>

#define NC 80
#define NP 30000
#define NG 800
#define NB 16384      // score buckets (2^14)
// gt y-bands
#define NYB 8
// pred bins: y-major, then width, then x (x fastest so consecutive preds share y/w)
#define NYBP 8
#define NWBP 2
#define NXBP 32
#define NPBIN (NYBP * NWBP * NXBP)   // 512

// ---------------- scratch (static device globals; no allocation) ----------------
__device__ unsigned long long g_slot[(size_t)NC * NP];   // (score_bits<<32)|idx, unsorted per bucket
__device__ unsigned int g_sbits[NC * NP];
__device__ int   g_hist[NC * NB];
__device__ int   g_base[NC * NB];
__device__ int   g_cursor[NC * NB];
__device__ int   g_xhist[NC * NPBIN];
__device__ int   g_xcursor[NC * NPBIN];
__device__ unsigned long long g_best[NC * NG];  // per-gt winner: (score<<32)|~idx
__device__ int   g_tpcnt[NC];
__device__ int   g_tprank[NC * 1024];
__device__ float g_ap[NC];
// compact boxes in input order
__device__ float4 g_pboxin[(size_t)NC * NP];
// preds sorted by (yband, wclass, xbin)
__device__ float4 g_pbox[(size_t)NC * NP];
__device__ int    g_pidx[NC * NP];
__device__ unsigned int g_pscore[NC * NP];
// gts sorted by (yband, x1)
__device__ float4 g_sgbox[NC * NG];
__device__ float  g_sgarea[NC * NG];
__device__ int    g_sgidx[NC * NG];
__device__ float  g_sgx1[NC * NG];
__device__ int    g_gbandoff[NC * (NYB + 1)];
__device__ float  g_gwmax[NC];
__device__ float  g_ghmax[NC];

__device__ __forceinline__ int sbucket(float s) {
    int b = (int)(s * 16384.0f);
    return max(0, min(b, NB - 1));
}
__device__ __forceinline__ int pbin(float x1, float y1, float w) {
    int xb = max(0, min((int)(x1 * ((float)NXBP / 1024.0f)), NXBP - 1));
    int yb = max(0, min((int)(y1 * ((float)NYBP / 1024.0f)), NYBP - 1));
    int wb = max(0, min((int)((w - 4.0f) * ((float)NWBP / 124.5f)), NWBP - 1));
    return (yb * NWBP + wb) * NXBP + xb;
}

// ---------------- K0: init ----------------
__global__ void k_init() {
    int i = blockIdx.x * blockDim.x + threadIdx.x;
    if (i < NC * NB)    g_hist[i] = 0;
    if (i < NC * NPBIN) g_xhist[i] = 0;
    if (i < NC * NG)    g_best[i] = 0ULL;
    if (i < NC)         g_tpcnt[i] = 0;
}

// ---------------- K1: histograms + stash compact boxes ----------------
__global__ void k_prep(const float* __restrict__ pred) {
    int i = blockIdx.x * blockDim.x + threadIdx.x;
    if (i >= NC * NP) return;
    const float* pp = pred + (size_t)i * 7;
    float s  = pp[2];
    float x1 = pp[3], y1 = pp[4], x2 = pp[5], y2 = pp[6];
    g_sbits[i]  = __float_as_uint(s);
    g_pboxin[i] = make_float4(x1, y1, x2, y2);
    int c = i / NP;
    atomicAdd(&g_hist[c * NB + sbucket(s)], 1);
    atomicAdd(&g_xhist[c * NPBIN + pbin(x1, y1, x2 - x1)], 1);
}

// ---------------- K2: per-class suffix-exclusive scan of score buckets ----------------
__global__ void k_scan() {
    __shared__ int ssum[1024];
    int c = blockIdx.x, t = threadIdx.x;
    int h[16], tot = 0;
    int off0 = c * NB + t * 16;
#pragma unroll
    for (int j = 0; j < 16; j++) { h[j] = g_hist[off0 + j]; tot += h[j]; }
    ssum[t] = tot;
    __syncthreads();
    for (int off = 1; off < 1024; off <<= 1) {
        int v = (t + off < 1024) ? ssum[t + off] : 0;
        __syncthreads();
        ssum[t] += v;
        __syncthreads();
    }
    int running = ssum[t] - tot;
#pragma unroll
    for (int j = 15; j >= 0; j--) {
        g_base[off0 + j]   = running;
        g_cursor[off0 + j] = running;
        running += h[j];
    }
}

// ---------------- K2b: per-class ascending exclusive scan of pred bins ----------------
__global__ void k_xscan() {
    __shared__ int sh[NPBIN];
    int c = blockIdx.x, t = threadIdx.x;
    sh[t] = g_xhist[c * NPBIN + t];
    __syncthreads();
    int v = sh[t];
    for (int off = 1; off < NPBIN; off <<= 1) {
        int u = (t >= off) ? sh[t - off] : 0;
        __syncthreads();
        sh[t] += u;
        __syncthreads();
    }
    g_xcursor[c * NPBIN + t] = sh[t] - v;   // exclusive prefix
}

// ---------------- K3: fused scatter (score slots + binned preds) ----------------
__global__ void k_fscatter() {
    int i = blockIdx.x * blockDim.x + threadIdx.x;
    if (i >= NC * NP) return;
    int c = i / NP, p = i - c * NP;
    unsigned int sb = g_sbits[i];
    float s = __uint_as_float(sb);
    int slot = atomicAdd(&g_cursor[c * NB + sbucket(s)], 1);
    g_slot[(size_t)c * NP + slot] = ((unsigned long long)sb << 32) | (unsigned int)p;

    float4 bx = g_pboxin[i];
    int bin = pbin(bx.x, bx.y, bx.z - bx.x);
    int xs = atomicAdd(&g_xcursor[c * NPBIN + bin], 1);
    g_pbox[(size_t)c * NP + xs] = bx;
    g_pidx[c * NP + xs] = p;
    g_pscore[c * NP + xs] = sb;
}

// ---------------- K4: per-class bitonic sort of gts by (yband, x1) ----------------
__global__ void k_gtsort(const float* __restrict__ gt) {
    __shared__ unsigned long long key[1024];
    __shared__ float swm[1024];
    __shared__ float shm[1024];
    int c = blockIdx.x, t = threadIdx.x;
    float w = 0.0f, h = 0.0f;
    if (t < NG) {
        const float* gp = gt + ((size_t)c * NG + t) * 7;
        float x1 = gp[3], y1 = gp[4];
        int band = max(0, min((int)(y1 * ((float)NYB / 1024.0f)), NYB - 1));
        key[t] = ((unsigned long long)band << 44)
               | ((unsigned long long)__float_as_uint(x1) << 12)
               | (unsigned int)t;
        w = gp[5] - x1;
        h = gp[6] - y1;
    } else {
        key[t] = 0xFFFFFFFFFFFFFFFFULL;
    }
    swm[t] = w;
    shm[t] = h;
    __syncthreads();
    for (int k2 = 2; k2 <= 1024; k2 <<= 1) {
        for (int j = k2 >> 1; j > 0; j >>= 1) {
            int ixj = t ^ j;
            if (ixj > t) {
                bool up = ((t & k2) == 0);
                unsigned long long a = key[t], b = key[ixj];
                if ((a > b) == up) { key[t] = b; key[ixj] = a; }
            }
            __syncthreads();
        }
    }
    for (int s = 512; s > 0; s >>= 1) {
        if (t < s) {
            swm[t] = fmaxf(swm[t], swm[t + s]);
            shm[t] = fmaxf(shm[t], shm[t + s]);
        }
        __syncthreads();
    }
    if (t == 0) { g_gwmax[c] = swm[0]; g_ghmax[c] = shm[0]; }
    if (t < NG) {
        int oi = (int)(key[t] & 0xFFFULL);
        const float* gp = gt + ((size_t)c * NG + oi) * 7;
        float x1 = gp[3], y1 = gp[4], x2 = gp[5], y2 = gp[6];
        int o = c * NG + t;
        g_sgbox[o]  = make_float4(x1, y1, x2, y2);
        g_sgarea[o] = (x2 - x1) * (y2 - y1);
        g_sgidx[o]  = oi;
        g_sgx1[o]   = x1;
    }
    // band offsets: first index with band >= b (padding keys are all-ones)
    if (t <= NYB) {
        unsigned long long thr = (unsigned long long)t << 44;
        int lo = 0, n = 1024;
        while (n > 0) {
            int half = n >> 1, mid = lo + half;
            if (key[mid] < thr) { lo = mid + 1; n -= half + 1; }
            else n = half;
        }
        g_gbandoff[c * (NYB + 1) + t] = min(lo, NG);
    }
}

// ---------------- K5: match — x-window * y-band pruning ----------------
#define MB 256
#define PPB (2 * MB)
#define SLACK 0.25f
__global__ void __launch_bounds__(MB) k_match() {
    __shared__ float4 sg[NG];
    __shared__ float  sa[NG];
    __shared__ int    si[NG];
    __shared__ float  sx[NG];
    __shared__ int    soff[NYB + 1];
    __shared__ float  s_wmax, s_hmax;
    int c = blockIdx.y;
    for (int g = threadIdx.x; g < NG; g += MB) {
        int o = c * NG + g;
        sg[g] = g_sgbox[o];
        sa[g] = g_sgarea[o];
        si[g] = g_sgidx[o];
        sx[g] = g_sgx1[o];
    }
    if (threadIdx.x <= NYB) soff[threadIdx.x] = g_gbandoff[c * (NYB + 1) + threadIdx.x];
    if (threadIdx.x == MB - 1) { s_wmax = g_gwmax[c]; s_hmax = g_ghmax[c]; }
    __syncthreads();

    // pair stride +32: warp covers 64 consecutive sorted preds (tight union window)
    int t = threadIdx.x;
    int j0 = blockIdx.x * PPB + (t >> 5) * 64 + (t & 31);
    int j1 = j0 + 32;
    if (j0 >= NP) return;
    bool v1 = j1 < NP;

    size_t cb = (size_t)c * NP;
    float4 A = g_pbox[cb + j0];
    float4 B = g_pbox[cb + (v1 ? j1 : j0)];
    float areaA = (A.z - A.x) * (A.w - A.y);
    float areaB = (B.z - B.x) * (B.w - B.y);

    // valid-winner strips (x and y): overlap must exceed w/3 resp. h/3
    float wA3 = (A.z - A.x) * (1.0f / 3.0f);
    float wB3 = (B.z - B.x) * (1.0f / 3.0f);
    float hA3 = (A.w - A.y) * (1.0f / 3.0f);
    float hB3 = (B.w - B.y) * (1.0f / 3.0f);
    float loX = fminf(A.x + wA3, B.x + wB3) - s_wmax - SLACK;
    float hiX = fmaxf(A.z - wA3, B.z - wB3) + SLACK;
    float loY = fminf(A.y + hA3, B.y + hB3) - s_hmax - SLACK;
    float hiY = fmaxf(A.w - hA3, B.w - hB3) + SLACK;

    int bLo = max(0, min((int)(loY * ((float)NYB / 1024.0f)), NYB - 1));
    int bHi = max(0, min((int)(hiY * ((float)NYB / 1024.0f)), NYB - 1));

    float ai = 0.0f, ad = 1.0f; int ag = 0;
    float bi = 0.0f, bd = 1.0f; int bg = 0;

    for (int b = bLo; b <= bHi; b++) {
        int s0 = soff[b], e0 = soff[b + 1];
        int lo = s0;
        {
            int n = e0 - s0;
            while (n > 0) {
                int half = n >> 1, mid = lo + half;
                if (sx[mid] < loX) { lo = mid + 1; n -= half + 1; }
                else n = half;
            }
        }
        int hi = lo;
        {
            int n = e0 - lo;
            while (n > 0) {
                int half = n >> 1, mid = hi + half;
                if (sx[mid] < hiX) { hi = mid + 1; n -= half + 1; }
                else n = half;
            }
        }
#pragma unroll 4
        for (int g = lo; g < hi; g++) {
            float4 q = sg[g];
            float ga = sa[g];

            float w0 = fminf(A.z, q.z) - fmaxf(A.x, q.x);
            float h0 = fminf(A.w, q.w) - fmaxf(A.y, q.y);
            float i0 = fmaxf(w0, 0.0f) * fmaxf(h0, 0.0f);
            float d0 = (areaA + ga) - i0;
            if (i0 * ad > ai * d0) { ai = i0; ad = d0; ag = g; }

            float w1 = fminf(B.z, q.z) - fmaxf(B.x, q.x);
            float h1 = fminf(B.w, q.w) - fmaxf(B.y, q.y);
            float i1 = fmaxf(w1, 0.0f) * fmaxf(h1, 0.0f);
            float d1 = (areaB + ga) - i1;
            if (i1 * bd > bi * d1) { bi = i1; bd = d1; bg = g; }
        }
    }

    {
        float iou = ai / (ad + 1e-9f);
        if (iou > 0.5f) {
            int agi = si[ag];
            unsigned int op = (unsigned int)g_pidx[c * NP + j0];
            unsigned long long key =
                ((unsigned long long)g_pscore[c * NP + j0] << 32) | (unsigned int)(~op);
            atomicMax(&g_best[c * NG + agi], key);
        }
    }
    if (v1) {
        float iou = bi / (bd + 1e-9f);
        if (iou > 0.5f) {
            int bgi = si[bg];
            unsigned int op = (unsigned int)g_pidx[c * NP + j1];
            unsigned long long key =
                ((unsigned long long)g_pscore[c * NP + j1] << 32) | (unsigned int)(~op);
            atomicMax(&g_best[c * NG + bgi], key);
        }
    }
}

// ---------------- K6: per-gt winner -> global rank (bucket count) ----------------
__global__ void k_collect() {
    int i = blockIdx.x * blockDim.x + threadIdx.x;
    if (i >= NC * NG) return;
    unsigned long long key = g_best[i];
    if (key == 0ULL) return;
    unsigned int sb = (unsigned int)(key >> 32);
    unsigned int op = ~((unsigned int)key);
    int c = i / NG;
    int b = sbucket(__uint_as_float(sb));
    int base = g_base[c * NB + b];
    int cnt  = g_hist[c * NB + b];
    const unsigned long long* s = g_slot + (size_t)c * NP + base;
    int better = 0;
    for (int k = 0; k < cnt; k++) {
        unsigned long long e = s[k];
        unsigned int qs = (unsigned int)(e >> 32);
        unsigned int qp = (unsigned int)e;
        better += (qs > sb) || (qs == sb && qp < op);
    }
    int rank = base + better;
    int t = atomicAdd(&g_tpcnt[c], 1);
    g_tprank[c * 1024 + t] = rank;
}

// ---------------- K7: per-class AP ----------------
__global__ void k_ap() {
    __shared__ int    sr[1024];
    __shared__ double red[1024];
    int c = blockIdx.x, t = threadIdx.x;
    int n = g_tpcnt[c];
    sr[t] = (t < n) ? g_tprank[c * 1024 + t] : 0x7fffffff;
    __syncthreads();
    double term = 0.0;
    if (t < n) {
        int r = sr[t];
        int cnt = 1;
        for (int j = 0; j < n; j++) cnt += (sr[j] < r) ? 1 : 0;
        if (r > 0) {
            float p1 = (float)cnt / (float)(r + 1);
            float p0 = (float)(cnt - 1) / (float)r;
            term = 0.5 * ((double)p1 + (double)p0);
        }
    }
    red[t] = term;
    __syncthreads();
    for (int s = 512; s > 0; s >>= 1) {
        if (t < s) red[t] += red[t + s];
        __syncthreads();
    }
    if (t == 0) g_ap[c] = (float)(red[0] / (double)NG);
}

// ---------------- K8: mean over classes ----------------
__global__ void k_mean(float* __restrict__ out) {
    __shared__ double red[128];
    int t = threadIdx.x;
    red[t] = (t < NC) ? (double)g_ap[t] : 0.0;
    __syncthreads();
    for (int s = 64; s > 0; s >>= 1) {
        if (t < s) red[t] += red[t + s];
        __syncthreads();
    }
    if (t == 0) out[0] = (float)(red[0] / (double)NC);
}

// ---------------- launcher ----------------
extern "C" void kernel_launch(void* const* d_in, const int* in_sizes, int n_in,
                              void* d_out, int out_size) {
    const float* pred;
    const float* gt;
    if (in_sizes[0] == NC * NP * 7) { pred = (const float*)d_in[0]; gt = (const float*)d_in[1]; }
    else                            { pred = (const float*)d_in[1]; gt = (const float*)d_in[0]; }

    const int NTOT = NC * NP;
    k_init<<<(NC * NB + 255) / 256, 256>>>();
    k_prep<<<(NTOT + 255) / 256, 256>>>(pred);
    k_scan<<<NC, 1024>>>();
    k_xscan<<<NC, NPBIN>>>();
    k_fscatter<<<(NTOT + 255) / 256, 256>>>();
    k_gtsort<<<NC, 1024>>>(gt);
    dim3 mg((NP + PPB - 1) / PPB, NC);
    k_match<<<mg, MB>>>();
    k_collect<<<(NC * NG + 255) / 256, 256>>>();
    k_ap<<<NC, 1024>>>();
    k_mean<<<1, 128>>>((float*)d_out);
}